// round 6
// baseline (speedup 1.0000x reference)
#include <cuda_runtime.h>

constexpr int VOCAB = 50257;
constexpr int DIM   = 50;
constexpr int NU2   = 64;
constexpr int NB    = 1024;
constexpr int NT    = 1024;

using u64 = unsigned long long;

// Precomputed embedding projection: embproj[v][k] = emb[v]@kx1[:,k] + b1[0][k]
// 50257*96 floats = 19.3 MB -> L2 resident during the recurrent kernel.
__device__ float g_embproj[(size_t)VOCAB * 96];

__device__ __forceinline__ u64 pack2(float lo, float hi) {
    u64 r; asm("mov.b64 %0, {%1, %2};" : "=l"(r) : "f"(lo), "f"(hi)); return r;
}
__device__ __forceinline__ u64 dup2(float v) { return pack2(v, v); }
__device__ __forceinline__ void unpack2(u64 p, float& lo, float& hi) {
    asm("mov.b64 {%0, %1}, %2;" : "=f"(lo), "=f"(hi) : "l"(p));
}
__device__ __forceinline__ u64 fma2(u64 a, u64 b, u64 c) {
    u64 d; asm("fma.rn.f32x2 %0, %1, %2, %3;" : "=l"(d) : "l"(a), "l"(b), "l"(c)); return d;
}
__device__ __forceinline__ u64 add2(u64 a, u64 b) {
    u64 d; asm("add.rn.f32x2 %0, %1, %2;" : "=l"(d) : "l"(a), "l"(b)); return d;
}
__device__ __forceinline__ float sigf(float x) {
    return __fdividef(1.0f, 1.0f + __expf(-x));
}
__device__ __forceinline__ float tanh_fast(float x) {
    return 1.0f - __fdividef(2.0f, 1.0f + __expf(2.0f * x));
}

// ---------------------------------------------------------------------------
// Kernel A: embproj = emb @ kx1 + b1[0]
// ---------------------------------------------------------------------------
__global__ void __launch_bounds__(96) embproj_kernel(const float* __restrict__ emb,
                                                     const float* __restrict__ kx1,
                                                     const float* __restrict__ b1) {
    __shared__ float kx1s[DIM * 96];
    __shared__ float xrow[DIM];
    const int tid = threadIdx.x;
    for (int i = tid; i < DIM * 96; i += 96) kx1s[i] = kx1[i];
    const float bc = b1[tid];
    __syncthreads();
    const int row0 = blockIdx.x * 16;
    for (int k = 0; k < 16; k++) {
        const int row = row0 + k;
        if (row >= VOCAB) break;
        if (tid < DIM) xrow[tid] = emb[(size_t)row * DIM + tid];
        __syncthreads();
        float acc = bc;
        #pragma unroll
        for (int d = 0; d < DIM; d++) acc = fmaf(xrow[d], kx1s[d * 96 + tid], acc);
        g_embproj[(size_t)row * 96 + tid] = acc;
        __syncthreads();
    }
}

// ---------------------------------------------------------------------------
// Kernel B: fused GRU1 -> GRU2 -> GLU -> dense.
// 128 blocks x 256 threads (8 warps). Block owns 8 elems; warp w owns elem w.
// kh2 (rows 8w..8w+8) and kx2 (rows 4w..4w+4) in REGISTERS, j-split across
// warps; rec2 partials held in registers across BAR1 and folded into the
// xproj2 partial store. Only kh1 weights come from smem per step.
//
// smem (floats):
//   [0,2048)       kh1zr  float2[32][32] {kh1[j][c], kh1[j][32+c]}
//   [2048,3072)    kh1h   float [32][32] kh1[j][64+c]
//   [3072,19456)   pX     u64[8 elems][8 warps][4][32]  (z, r, x_h, rec_h)
//   [19456,19712)  h1s    float[8][32]
//   [19712,20224)  h2s    float[8][64]
// ---------------------------------------------------------------------------
constexpr int SMEM_FLOATS = 3072 + 16384 + 256 + 512;  // 20224 floats = 79 KB

__global__ void __launch_bounds__(256, 1) rnn_kernel(
    const int*   __restrict__ tokens,
    const float* __restrict__ kh1, const float* __restrict__ b1,
    const float* __restrict__ kx2, const float* __restrict__ kh2,
    const float* __restrict__ b2,
    const float* __restrict__ wg,  const float* __restrict__ bg,
    const float* __restrict__ wd,  const float* __restrict__ bd,
    float* __restrict__ out)
{
    extern __shared__ float smem[];
    float2* kh1zr = (float2*)smem;                 // [32][32]
    float*  kh1h  = smem + 2048;                   // [32][32]
    u64*    pX    = (u64*)(smem + 3072);           // [8][8][4][32]
    float*  h1s   = smem + 3072 + 16384;           // [8][32]
    float*  h2s   = h1s + 256;                     // [8][64]

    const int tid = threadIdx.x;

    for (int i = tid; i < 1024; i += 256) {
        const int j = i >> 5, c = i & 31;
        kh1zr[i] = make_float2(kh1[j * 96 + c], kh1[j * 96 + 32 + c]);
        kh1h[i]  = kh1[j * 96 + 64 + c];
    }
    if (tid < 256) h1s[tid] = 0.0f;
    for (int i = tid; i < 512; i += 256) h2s[i] = 0.0f;
    __syncthreads();

    const int wid = tid >> 5;
    const int l   = tid & 31;

    // kh2 rows [8w, 8w+8): lane l owns col pairs (l,l+32) per gate
    u64 wz2[8], wr2[8], wh2[8];
    {
        const float* base = kh2 + (size_t)(wid * 8) * 192;
        #pragma unroll
        for (int jj = 0; jj < 8; jj++) {
            const float* r = base + jj * 192;
            wz2[jj] = pack2(__ldg(r + l),       __ldg(r + 32 + l));
            wr2[jj] = pack2(__ldg(r + 64 + l),  __ldg(r + 96 + l));
            wh2[jj] = pack2(__ldg(r + 128 + l), __ldg(r + 160 + l));
        }
    }
    // kx2 rows [4w, 4w+4)
    u64 xw0[4], xw1[4], xw2[4];
    {
        const float* base = kx2 + (size_t)(wid * 4) * 192;
        #pragma unroll
        for (int jj = 0; jj < 4; jj++) {
            const float* r = base + jj * 192;
            xw0[jj] = pack2(__ldg(r + l),       __ldg(r + 32 + l));
            xw1[jj] = pack2(__ldg(r + 64 + l),  __ldg(r + 96 + l));
            xw2[jj] = pack2(__ldg(r + 128 + l), __ldg(r + 160 + l));
        }
    }

    // biases
    const u64 azr1b = pack2(__ldg(b1 + 96 + l), __ldg(b1 + 128 + l));
    const float bg1 = __ldg(b1 + 160 + l);
    const u64 bz2  = pack2(__ldg(b2 + l)      + __ldg(b2 + 192 + l),
                           __ldg(b2 + 32 + l) + __ldg(b2 + 224 + l));
    const u64 br2  = pack2(__ldg(b2 + 64 + l) + __ldg(b2 + 256 + l),
                           __ldg(b2 + 96 + l) + __ldg(b2 + 288 + l));
    const u64 bxh2 = pack2(__ldg(b2 + 128 + l), __ldg(b2 + 160 + l));
    const u64 bhh2 = pack2(__ldg(b2 + 320 + l), __ldg(b2 + 352 + l));

    const int eg = blockIdx.x * 8 + wid;          // global elem owned by warp
    const int* tok = tokens + (size_t)eg * NT;

    float h1o = 0.0f, h2a = 0.0f, h2b = 0.0f;
    int tk = 0;

    for (int t = 0; t < NT; t++) {
        if ((t & 31) == 0) tk = tok[t + l];
        const int ti = __shfl_sync(0xffffffffu, tk, t & 31);
        const float* ep = g_embproj + (size_t)ti * 96;
        const float xz = __ldg(ep + l), xr = __ldg(ep + 32 + l), xh = __ldg(ep + 64 + l);

        // ===== Stage B1: rec2 partials for ALL 8 elems (kh2 rows 8w..8w+8) ==
        // Held in registers across BAR1 (24 u64).
        u64 azR[8], arR[8], ahR[8];
        #pragma unroll
        for (int e = 0; e < 8; e++) {
            const float4* hv = (const float4*)(h2s + e * 64 + wid * 8);
            const float4 v0 = hv[0], v1 = hv[1];
            u64 az = 0ull, ar = 0ull, ah = 0ull, d;
            d = dup2(v0.x); az = fma2(wz2[0], d, az); ar = fma2(wr2[0], d, ar); ah = fma2(wh2[0], d, ah);
            d = dup2(v0.y); az = fma2(wz2[1], d, az); ar = fma2(wr2[1], d, ar); ah = fma2(wh2[1], d, ah);
            d = dup2(v0.z); az = fma2(wz2[2], d, az); ar = fma2(wr2[2], d, ar); ah = fma2(wh2[2], d, ah);
            d = dup2(v0.w); az = fma2(wz2[3], d, az); ar = fma2(wr2[3], d, ar); ah = fma2(wh2[3], d, ah);
            d = dup2(v1.x); az = fma2(wz2[4], d, az); ar = fma2(wr2[4], d, ar); ah = fma2(wh2[4], d, ah);
            d = dup2(v1.y); az = fma2(wz2[5], d, az); ar = fma2(wr2[5], d, ar); ah = fma2(wh2[5], d, ah);
            d = dup2(v1.z); az = fma2(wz2[6], d, az); ar = fma2(wr2[6], d, ar); ah = fma2(wh2[6], d, ah);
            d = dup2(v1.w); az = fma2(wz2[7], d, az); ar = fma2(wr2[7], d, ar); ah = fma2(wh2[7], d, ah);
            azR[e] = az; arR[e] = ar; ahR[e] = ah;
        }

        // ===== Stage B2: GRU1 for own elem (kh1 from smem) ==================
        u64 azr = azr1b; float ah1 = bg1;
        {
            const float4* hA4 = (const float4*)(h1s + wid * 32);
            #pragma unroll
            for (int j4 = 0; j4 < 8; j4++) {
                const float4 hA = hA4[j4];
                #pragma unroll
                for (int jj = 0; jj < 4; jj++) {
                    const int j = j4 * 4 + jj;
                    const u64 wzr   = ((const u64*)kh1zr)[j * 32 + l];
                    const float whv = kh1h[j * 32 + l];
                    const float va  = (&hA.x)[jj];
                    azr = fma2(wzr, dup2(va), azr);
                    ah1 = fmaf(whv, va, ah1);
                }
            }
        }
        {
            float az, ar; unpack2(azr, az, ar);
            const float z = sigf(xz + az), r = sigf(xr + ar);
            const float hh = tanh_fast(xh + r * ah1);
            h1o = z * h1o + (1.0f - z) * hh;
        }
        __syncwarp();                 // all lanes done reading h1s before overwrite
        h1s[wid * 32 + l] = h1o;
        __syncthreads();              // BAR1: h1(t) + h2s reads complete

        // ===== Stage C: xproj2 partials (kx2 rows 4w..4w+4), fold rec2, STS =
        #pragma unroll
        for (int e = 0; e < 8; e++) {
            const float4 hv = *(const float4*)(h1s + e * 32 + wid * 4);
            u64 az = 0ull, ar = 0ull, ax = 0ull, d;
            d = dup2(hv.x); az = fma2(xw0[0], d, az); ar = fma2(xw1[0], d, ar); ax = fma2(xw2[0], d, ax);
            d = dup2(hv.y); az = fma2(xw0[1], d, az); ar = fma2(xw1[1], d, ar); ax = fma2(xw2[1], d, ax);
            d = dup2(hv.z); az = fma2(xw0[2], d, az); ar = fma2(xw1[2], d, ar); ax = fma2(xw2[2], d, ax);
            d = dup2(hv.w); az = fma2(xw0[3], d, az); ar = fma2(xw1[3], d, ar); ax = fma2(xw2[3], d, ax);
            u64* pb = pX + (size_t)((e * 8 + wid) * 4) * 32 + l;
            pb[0]  = add2(az, azR[e]);   // z: x-side + rec-side
            pb[32] = add2(ar, arR[e]);   // r
            pb[64] = ax;                 // h x-side (kept separate for reset gate)
            pb[96] = ahR[e];             // h rec-side
        }
        __syncthreads();              // BAR2: partials published

        // ===== Stage D: combine own elem, GRU2 gates, publish h2 ============
        u64 zp = bz2, rp = br2, xp = bxh2, hm = bhh2;
        #pragma unroll
        for (int w = 0; w < 8; w++) {
            const u64* pb = pX + (size_t)((wid * 8 + w) * 4) * 32 + l;
            zp = add2(zp, pb[0]);
            rp = add2(rp, pb[32]);
            xp = add2(xp, pb[64]);
            hm = add2(hm, pb[96]);
        }
        float zl, zh_, rl, rh_, xpl, xph, ml, mh;
        unpack2(zp, zl, zh_); unpack2(rp, rl, rh_);
        unpack2(xp, xpl, xph); unpack2(hm, ml, mh);
        {
            const float z = sigf(zl), r = sigf(rl);
            const float hh = tanh_fast(xpl + r * ml);
            h2a = z * h2a + (1.0f - z) * hh;
        }
        {
            const float z = sigf(zh_), r = sigf(rh_);
            const float hh = tanh_fast(xph + r * mh);
            h2b = z * h2b + (1.0f - z) * hh;
        }
        h2s[wid * 64 + l]      = h2a;
        h2s[wid * 64 + 32 + l] = h2b;
        __syncthreads();              // BAR3: h2(t) published; pX reusable
    }

    // ---------------- head: a = h2@wg + bg ; GLU ; sigmoid(x@wd + bd) -------
    {
        const float* h2e = h2s + wid * 64;
        float acc[8];
        #pragma unroll
        for (int k = 0; k < 8; k++) acc[k] = __ldg(bg + l + 32 * k);
        for (int j = 0; j < NU2; j++) {
            const float hv = h2e[j];
            const float* wrp = wg + j * 256 + l;
            #pragma unroll
            for (int k = 0; k < 8; k++) acc[k] = fmaf(hv, __ldg(wrp + 32 * k), acc[k]);
        }
        float s = 0.0f;
        #pragma unroll
        for (int k = 0; k < 4; k++) {
            const float g = acc[k] * sigf(acc[k + 4]);
            s = fmaf(g, __ldg(wd + l + 32 * k), s);
        }
        #pragma unroll
        for (int off = 16; off >= 1; off >>= 1) s += __shfl_xor_sync(0xffffffffu, s, off);
        if (l == 0) out[eg] = sigf(s + __ldg(bd));
    }
}

// ---------------------------------------------------------------------------
extern "C" void kernel_launch(void* const* d_in, const int* in_sizes, int n_in,
                              void* d_out, int out_size) {
    const int*   tokens = (const int*)d_in[0];
    const float* emb = (const float*)d_in[1];
    const float* kx1 = (const float*)d_in[2];
    const float* kh1 = (const float*)d_in[3];
    const float* b1  = (const float*)d_in[4];
    const float* kx2 = (const float*)d_in[5];
    const float* kh2 = (const float*)d_in[6];
    const float* b2  = (const float*)d_in[7];
    const float* wg  = (const float*)d_in[8];
    const float* bg  = (const float*)d_in[9];
    const float* wd  = (const float*)d_in[10];
    const float* bd  = (const float*)d_in[11];
    float* out = (float*)d_out;

    const size_t smem_bytes = SMEM_FLOATS * sizeof(float);
    cudaFuncSetAttribute(rnn_kernel, cudaFuncAttributeMaxDynamicSharedMemorySize, (int)smem_bytes);

    embproj_kernel<<<(VOCAB + 15) / 16, 96>>>(emb, kx1, b1);
    rnn_kernel<<<NB / 8, 256, smem_bytes>>>(tokens, kh1, b1, kx2, kh2, b2, wg, bg, wd, bd, out);
}

// round 7
// speedup vs baseline: 1.2612x; 1.2612x over previous
#include <cuda_runtime.h>

constexpr int VOCAB = 50257;
constexpr int DIM   = 50;
constexpr int NU2   = 64;
constexpr int NB    = 1024;
constexpr int NT    = 1024;

using u64 = unsigned long long;

// Precomputed embedding projection: embproj[v][k] = emb[v]@kx1[:,k] + b1[0][k]
// 50257*96 floats = 19.3 MB -> L2 resident during the recurrent kernel.
__device__ float g_embproj[(size_t)VOCAB * 96];

__device__ __forceinline__ u64 pack2(float lo, float hi) {
    u64 r; asm("mov.b64 %0, {%1, %2};" : "=l"(r) : "f"(lo), "f"(hi)); return r;
}
__device__ __forceinline__ u64 dup2(float v) { return pack2(v, v); }
__device__ __forceinline__ void unpack2(u64 p, float& lo, float& hi) {
    asm("mov.b64 {%0, %1}, %2;" : "=f"(lo), "=f"(hi) : "l"(p));
}
__device__ __forceinline__ u64 fma2(u64 a, u64 b, u64 c) {
    u64 d; asm("fma.rn.f32x2 %0, %1, %2, %3;" : "=l"(d) : "l"(a), "l"(b), "l"(c)); return d;
}
__device__ __forceinline__ u64 add2(u64 a, u64 b) {
    u64 d; asm("add.rn.f32x2 %0, %1, %2;" : "=l"(d) : "l"(a), "l"(b)); return d;
}
__device__ __forceinline__ float sigf(float x) {
    return __fdividef(1.0f, 1.0f + __expf(-x));
}
__device__ __forceinline__ float tanh_fast(float x) {
    return 1.0f - __fdividef(2.0f, 1.0f + __expf(2.0f * x));
}

// ---------------------------------------------------------------------------
// Kernel A: embproj = emb @ kx1 + b1[0]
// ---------------------------------------------------------------------------
__global__ void __launch_bounds__(96) embproj_kernel(const float* __restrict__ emb,
                                                     const float* __restrict__ kx1,
                                                     const float* __restrict__ b1) {
    __shared__ float kx1s[DIM * 96];
    __shared__ float xrow[DIM];
    const int tid = threadIdx.x;
    for (int i = tid; i < DIM * 96; i += 96) kx1s[i] = kx1[i];
    const float bc = b1[tid];
    __syncthreads();
    const int row0 = blockIdx.x * 16;
    for (int k = 0; k < 16; k++) {
        const int row = row0 + k;
        if (row >= VOCAB) break;
        if (tid < DIM) xrow[tid] = emb[(size_t)row * DIM + tid];
        __syncthreads();
        float acc = bc;
        #pragma unroll
        for (int d = 0; d < DIM; d++) acc = fmaf(xrow[d], kx1s[d * 96 + tid], acc);
        g_embproj[(size_t)row * 96 + tid] = acc;
        __syncthreads();
    }
}

// ---------------------------------------------------------------------------
// Kernel B: fused GRU1 -> GRU2 -> GLU -> dense.
// 256 blocks x 128 threads (4 warps); 2 CTAs co-resident per SM so one CTA's
// barrier/latency stalls are covered by the other (independent) CTA.
// Block owns 4 elems; warp w owns elem w. kh2 rows [16w,16w+16) and kx2 rows
// [8w,8w+8) in REGISTERS; rec2 partials carried in registers across BAR1 and
// folded into the xproj2 partial store. Only kh1 comes from smem per step.
//
// smem (floats):
//   [0,2048)      kh1zr  float2[32][32] {kh1[j][c], kh1[j][32+c]}
//   [2048,3072)   kh1h   float [32][32] kh1[j][64+c]
//   [3072,7168)   pX     u64[4 elems][4 warps][4][32] (z, r, x_h, rec_h)
//   [7168,7296)   h1s    float[4][32]
//   [7296,7552)   h2s    float[4][64]
// ---------------------------------------------------------------------------
constexpr int SMEM_FLOATS = 3072 + 4096 + 128 + 256;   // 7552 floats = 29.5 KB

__global__ void __launch_bounds__(128, 2) rnn_kernel(
    const int*   __restrict__ tokens,
    const float* __restrict__ kh1, const float* __restrict__ b1,
    const float* __restrict__ kx2, const float* __restrict__ kh2,
    const float* __restrict__ b2,
    const float* __restrict__ wg,  const float* __restrict__ bg,
    const float* __restrict__ wd,  const float* __restrict__ bd,
    float* __restrict__ out)
{
    extern __shared__ float smem[];
    float2* kh1zr = (float2*)smem;                 // [32][32]
    float*  kh1h  = smem + 2048;                   // [32][32]
    u64*    pX    = (u64*)(smem + 3072);           // [4][4][4][32]
    float*  h1s   = smem + 3072 + 4096;            // [4][32]
    float*  h2s   = h1s + 128;                     // [4][64]

    const int tid = threadIdx.x;

    for (int i = tid; i < 1024; i += 128) {
        const int j = i >> 5, c = i & 31;
        kh1zr[i] = make_float2(kh1[j * 96 + c], kh1[j * 96 + 32 + c]);
        kh1h[i]  = kh1[j * 96 + 64 + c];
    }
    if (tid < 128) h1s[tid] = 0.0f;
    for (int i = tid; i < 256; i += 128) h2s[i] = 0.0f;
    __syncthreads();

    const int wid = tid >> 5;
    const int l   = tid & 31;

    // kh2 rows [16w, 16w+16): lane l owns col pairs (l,l+32) per gate
    u64 wz2[16], wr2[16], wh2[16];
    {
        const float* base = kh2 + (size_t)(wid * 16) * 192;
        #pragma unroll
        for (int jj = 0; jj < 16; jj++) {
            const float* r = base + jj * 192;
            wz2[jj] = pack2(__ldg(r + l),       __ldg(r + 32 + l));
            wr2[jj] = pack2(__ldg(r + 64 + l),  __ldg(r + 96 + l));
            wh2[jj] = pack2(__ldg(r + 128 + l), __ldg(r + 160 + l));
        }
    }
    // kx2 rows [8w, 8w+8)
    u64 xw0[8], xw1[8], xw2[8];
    {
        const float* base = kx2 + (size_t)(wid * 8) * 192;
        #pragma unroll
        for (int jj = 0; jj < 8; jj++) {
            const float* r = base + jj * 192;
            xw0[jj] = pack2(__ldg(r + l),       __ldg(r + 32 + l));
            xw1[jj] = pack2(__ldg(r + 64 + l),  __ldg(r + 96 + l));
            xw2[jj] = pack2(__ldg(r + 128 + l), __ldg(r + 160 + l));
        }
    }

    // biases
    const u64 azr1b = pack2(__ldg(b1 + 96 + l), __ldg(b1 + 128 + l));
    const float bg1 = __ldg(b1 + 160 + l);
    const u64 bz2  = pack2(__ldg(b2 + l)      + __ldg(b2 + 192 + l),
                           __ldg(b2 + 32 + l) + __ldg(b2 + 224 + l));
    const u64 br2  = pack2(__ldg(b2 + 64 + l) + __ldg(b2 + 256 + l),
                           __ldg(b2 + 96 + l) + __ldg(b2 + 288 + l));
    const u64 bxh2 = pack2(__ldg(b2 + 128 + l), __ldg(b2 + 160 + l));
    const u64 bhh2 = pack2(__ldg(b2 + 320 + l), __ldg(b2 + 352 + l));

    const int eg = blockIdx.x * 4 + wid;          // global elem owned by warp
    const int* tok = tokens + (size_t)eg * NT;

    float h1o = 0.0f, h2a = 0.0f, h2b = 0.0f;
    int tk = 0;

    for (int t = 0; t < NT; t++) {
        if ((t & 31) == 0) tk = tok[t + l];
        const int ti = __shfl_sync(0xffffffffu, tk, t & 31);
        const float* ep = g_embproj + (size_t)ti * 96;
        const float xz = __ldg(ep + l), xr = __ldg(ep + 32 + l), xh = __ldg(ep + 64 + l);

        // ===== Stage B1: rec2 partials for ALL 4 elems (kh2 rows 16w..16w+16)
        u64 azR[4], arR[4], ahR[4];
        #pragma unroll
        for (int e = 0; e < 4; e++) {
            const float4* hv = (const float4*)(h2s + e * 64 + wid * 16);
            u64 az = 0ull, ar = 0ull, ah = 0ull;
            #pragma unroll
            for (int q = 0; q < 4; q++) {
                const float4 v = hv[q];
                u64 d;
                d = dup2(v.x); az = fma2(wz2[q*4+0], d, az); ar = fma2(wr2[q*4+0], d, ar); ah = fma2(wh2[q*4+0], d, ah);
                d = dup2(v.y); az = fma2(wz2[q*4+1], d, az); ar = fma2(wr2[q*4+1], d, ar); ah = fma2(wh2[q*4+1], d, ah);
                d = dup2(v.z); az = fma2(wz2[q*4+2], d, az); ar = fma2(wr2[q*4+2], d, ar); ah = fma2(wh2[q*4+2], d, ah);
                d = dup2(v.w); az = fma2(wz2[q*4+3], d, az); ar = fma2(wr2[q*4+3], d, ar); ah = fma2(wh2[q*4+3], d, ah);
            }
            azR[e] = az; arR[e] = ar; ahR[e] = ah;
        }

        // ===== Stage B2: GRU1 for own elem (kh1 from smem) ==================
        u64 azr = azr1b; float ah1 = bg1;
        {
            const float4* hA4 = (const float4*)(h1s + wid * 32);
            #pragma unroll
            for (int j4 = 0; j4 < 8; j4++) {
                const float4 hA = hA4[j4];
                #pragma unroll
                for (int jj = 0; jj < 4; jj++) {
                    const int j = j4 * 4 + jj;
                    const u64 wzr   = ((const u64*)kh1zr)[j * 32 + l];
                    const float whv = kh1h[j * 32 + l];
                    const float va  = (&hA.x)[jj];
                    azr = fma2(wzr, dup2(va), azr);
                    ah1 = fmaf(whv, va, ah1);
                }
            }
        }
        {
            float az, ar; unpack2(azr, az, ar);
            const float z = sigf(xz + az), r = sigf(xr + ar);
            const float hh = tanh_fast(xh + r * ah1);
            h1o = z * h1o + (1.0f - z) * hh;
        }
        __syncwarp();                 // lanes done reading h1s before overwrite
        h1s[wid * 32 + l] = h1o;
        __syncthreads();              // BAR1: h1(t) published; h2s reads done

        // ===== Stage C: xproj2 partials (kx2 rows 8w..8w+8), fold rec2, STS =
        #pragma unroll
        for (int e = 0; e < 4; e++) {
            const float4* hvp = (const float4*)(h1s + e * 32 + wid * 8);
            const float4 v0 = hvp[0], v1 = hvp[1];
            u64 az = 0ull, ar = 0ull, ax = 0ull, d;
            d = dup2(v0.x); az = fma2(xw0[0], d, az); ar = fma2(xw1[0], d, ar); ax = fma2(xw2[0], d, ax);
            d = dup2(v0.y); az = fma2(xw0[1], d, az); ar = fma2(xw1[1], d, ar); ax = fma2(xw2[1], d, ax);
            d = dup2(v0.z); az = fma2(xw0[2], d, az); ar = fma2(xw1[2], d, ar); ax = fma2(xw2[2], d, ax);
            d = dup2(v0.w); az = fma2(xw0[3], d, az); ar = fma2(xw1[3], d, ar); ax = fma2(xw2[3], d, ax);
            d = dup2(v1.x); az = fma2(xw0[4], d, az); ar = fma2(xw1[4], d, ar); ax = fma2(xw2[4], d, ax);
            d = dup2(v1.y); az = fma2(xw0[5], d, az); ar = fma2(xw1[5], d, ar); ax = fma2(xw2[5], d, ax);
            d = dup2(v1.z); az = fma2(xw0[6], d, az); ar = fma2(xw1[6], d, ar); ax = fma2(xw2[6], d, ax);
            d = dup2(v1.w); az = fma2(xw0[7], d, az); ar = fma2(xw1[7], d, ar); ax = fma2(xw2[7], d, ax);
            u64* pb = pX + (size_t)((e * 4 + wid) * 4) * 32 + l;
            pb[0]  = add2(az, azR[e]);   // z: x-side + rec-side
            pb[32] = add2(ar, arR[e]);   // r
            pb[64] = ax;                 // h x-side (kept separate for reset)
            pb[96] = ahR[e];             // h rec-side
        }
        __syncthreads();              // BAR2: partials published

        // ===== Stage D: combine own elem, GRU2 gates, publish h2 ============
        u64 zp = bz2, rp = br2, xp = bxh2, hm = bhh2;
        #pragma unroll
        for (int w = 0; w < 4; w++) {
            const u64* pb = pX + (size_t)((wid * 4 + w) * 4) * 32 + l;
            zp = add2(zp, pb[0]);
            rp = add2(rp, pb[32]);
            xp = add2(xp, pb[64]);
            hm = add2(hm, pb[96]);
        }
        float zl, zh_, rl, rh_, xpl, xph, ml, mh;
        unpack2(zp, zl, zh_); unpack2(rp, rl, rh_);
        unpack2(xp, xpl, xph); unpack2(hm, ml, mh);
        {
            const float z = sigf(zl), r = sigf(rl);
            const float hh = tanh_fast(xpl + r * ml);
            h2a = z * h2a + (1.0f - z) * hh;
        }
        {
            const float z = sigf(zh_), r = sigf(rh_);
            const float hh = tanh_fast(xph + r * mh);
            h2b = z * h2b + (1.0f - z) * hh;
        }
        h2s[wid * 64 + l]      = h2a;
        h2s[wid * 64 + 32 + l] = h2b;
        __syncthreads();              // BAR3: h2(t) published; pX reusable
    }

    // ---------------- head: a = h2@wg + bg ; GLU ; sigmoid(x@wd + bd) -------
    {
        const float* h2e = h2s + wid * 64;
        float acc[8];
        #pragma unroll
        for (int k = 0; k < 8; k++) acc[k] = __ldg(bg + l + 32 * k);
        for (int j = 0; j < NU2; j++) {
            const float hv = h2e[j];
            const float* wrp = wg + j * 256 + l;
            #pragma unroll
            for (int k = 0; k < 8; k++) acc[k] = fmaf(hv, __ldg(wrp + 32 * k), acc[k]);
        }
        float s = 0.0f;
        #pragma unroll
        for (int k = 0; k < 4; k++) {
            const float g = acc[k] * sigf(acc[k + 4]);
            s = fmaf(g, __ldg(wd + l + 32 * k), s);
        }
        #pragma unroll
        for (int off = 16; off >= 1; off >>= 1) s += __shfl_xor_sync(0xffffffffu, s, off);
        if (l == 0) out[eg] = sigf(s + __ldg(bd));
    }
}

// ---------------------------------------------------------------------------
extern "C" void kernel_launch(void* const* d_in, const int* in_sizes, int n_in,
                              void* d_out, int out_size) {
    const int*   tokens = (const int*)d_in[0];
    const float* emb = (const float*)d_in[1];
    const float* kx1 = (const float*)d_in[2];
    const float* kh1 = (const float*)d_in[3];
    const float* b1  = (const float*)d_in[4];
    const float* kx2 = (const float*)d_in[5];
    const float* kh2 = (const float*)d_in[6];
    const float* b2  = (const float*)d_in[7];
    const float* wg  = (const float*)d_in[8];
    const float* bg  = (const float*)d_in[9];
    const float* wd  = (const float*)d_in[10];
    const float* bd  = (const float*)d_in[11];
    float* out = (float*)d_out;

    const size_t smem_bytes = SMEM_FLOATS * sizeof(float);
    cudaFuncSetAttribute(rnn_kernel, cudaFuncAttributeMaxDynamicSharedMemorySize, (int)smem_bytes);

    embproj_kernel<<<(VOCAB + 15) / 16, 96>>>(emb, kx1, b1);
    rnn_kernel<<<NB / 4, 128, smem_bytes>>>(tokens, kh1, b1, kx2, kh2, b2, wg, bg, wd, bd, out);
}

// round 9
// speedup vs baseline: 1.3671x; 1.0840x over previous
#include <cuda_runtime.h>

constexpr int VOCAB = 50257;
constexpr int DIM   = 50;
constexpr int NU2   = 64;
constexpr int NB    = 1024;
constexpr int NT    = 1024;

using u64 = unsigned long long;

// Precomputed embedding projection: embproj[v][k] = emb[v]@kx1[:,k] + b1[0][k]
// 50257*96 floats = 19.3 MB -> L2 resident during the recurrent kernel.
__device__ float g_embproj[(size_t)VOCAB * 96];

__device__ __forceinline__ u64 pack2(float lo, float hi) {
    u64 r; asm("mov.b64 %0, {%1, %2};" : "=l"(r) : "f"(lo), "f"(hi)); return r;
}
__device__ __forceinline__ u64 dup2(float v) { return pack2(v, v); }
__device__ __forceinline__ void unpack2(u64 p, float& lo, float& hi) {
    asm("mov.b64 {%0, %1}, %2;" : "=f"(lo), "=f"(hi) : "l"(p));
}
__device__ __forceinline__ u64 fma2(u64 a, u64 b, u64 c) {
    u64 d; asm("fma.rn.f32x2 %0, %1, %2, %3;" : "=l"(d) : "l"(a), "l"(b), "l"(c)); return d;
}
__device__ __forceinline__ u64 add2(u64 a, u64 b) {
    u64 d; asm("add.rn.f32x2 %0, %1, %2;" : "=l"(d) : "l"(a), "l"(b)); return d;
}
__device__ __forceinline__ float sigf(float x) {
    return __fdividef(1.0f, 1.0f + __expf(-x));
}
__device__ __forceinline__ float tanh_fast(float x) {
    return 1.0f - __fdividef(2.0f, 1.0f + __expf(2.0f * x));
}

// ---------------------------------------------------------------------------
// Kernel A: embproj = emb @ kx1 + b1[0]
// ---------------------------------------------------------------------------
__global__ void __launch_bounds__(96) embproj_kernel(const float* __restrict__ emb,
                                                     const float* __restrict__ kx1,
                                                     const float* __restrict__ b1) {
    __shared__ float kx1s[DIM * 96];
    __shared__ float xrow[DIM];
    const int tid = threadIdx.x;
    for (int i = tid; i < DIM * 96; i += 96) kx1s[i] = kx1[i];
    const float bc = b1[tid];
    __syncthreads();
    const int row0 = blockIdx.x * 16;
    for (int k = 0; k < 16; k++) {
        const int row = row0 + k;
        if (row >= VOCAB) break;
        if (tid < DIM) xrow[tid] = emb[(size_t)row * DIM + tid];
        __syncthreads();
        float acc = bc;
        #pragma unroll
        for (int d = 0; d < DIM; d++) acc = fmaf(xrow[d], kx1s[d * 96 + tid], acc);
        g_embproj[(size_t)row * 96 + tid] = acc;
        __syncthreads();
    }
}

// ---------------------------------------------------------------------------
// Kernel B: fused GRU1 -> GRU2 -> GLU -> dense.
// 296 blocks x 128 threads: EXACTLY 2 CTAs per SM (296 = 2*148), so CTA load
// is balanced chip-wide. Blocks [0,136) own 4 elems; [136,296) own 3 elems.
// Warp w owns elem w (if w < NE). kh2 rows [16w,16w+16) and kx2 rows
// [8w,8w+8) in REGISTERS; rec2 partials carried in registers across BAR1 and
// folded into the xproj2 partial store. Only kh1 comes from smem per step.
//
// smem (floats):
//   [0,2048)      kh1zr  float2[32][32] {kh1[j][c], kh1[j][32+c]}
//   [2048,3072)   kh1h   float [32][32] kh1[j][64+c]
//   [3072,7168)   pX     u64[4 elems][4 warps][4][32] (z, r, x_h, rec_h)
//   [7168,7296)   h1s    float[4][32]
//   [7296,7552)   h2s    float[4][64]
// ---------------------------------------------------------------------------
constexpr int SMEM_FLOATS = 3072 + 4096 + 128 + 256;   // 7552 floats = 29.5 KB

struct RnnArgs {
    const int* tok;          // this warp's token row
    const float2* kh1zr;
    const float* kh1h;
    u64*   pX;
    float* h1s;
    float* h2s;
    int    wid, l;
    bool   owns;             // wid < NE
    // biases
    u64 azr1b; float bg1;
    u64 bz2, br2, bxh2, bhh2;
};

template<int NE>
__device__ __forceinline__ void rnn_scan(
    const RnnArgs& A,
    const u64* wz2, const u64* wr2, const u64* wh2,
    const u64* xw0, const u64* xw1, const u64* xw2,
    float& h1o, float& h2a, float& h2b)
{
    const int wid = A.wid, l = A.l;
    int tk = 0;
    for (int t = 0; t < NT; t++) {
        if ((t & 31) == 0) tk = A.tok[t + l];
        const int ti = __shfl_sync(0xffffffffu, tk, t & 31);
        const float* ep = g_embproj + (size_t)ti * 96;
        const float xz = __ldg(ep + l), xr = __ldg(ep + 32 + l), xh = __ldg(ep + 64 + l);

        // ===== Stage B1: rec2 partials for NE elems (kh2 rows 16w..16w+16) ==
        u64 azR[NE], arR[NE], ahR[NE];
        #pragma unroll
        for (int e = 0; e < NE; e++) {
            const float4* hv = (const float4*)(A.h2s + e * 64 + wid * 16);
            u64 az = 0ull, ar = 0ull, ah = 0ull;
            #pragma unroll
            for (int q = 0; q < 4; q++) {
                const float4 v = hv[q];
                u64 d;
                d = dup2(v.x); az = fma2(wz2[q*4+0], d, az); ar = fma2(wr2[q*4+0], d, ar); ah = fma2(wh2[q*4+0], d, ah);
                d = dup2(v.y); az = fma2(wz2[q*4+1], d, az); ar = fma2(wr2[q*4+1], d, ar); ah = fma2(wh2[q*4+1], d, ah);
                d = dup2(v.z); az = fma2(wz2[q*4+2], d, az); ar = fma2(wr2[q*4+2], d, ar); ah = fma2(wh2[q*4+2], d, ah);
                d = dup2(v.w); az = fma2(wz2[q*4+3], d, az); ar = fma2(wr2[q*4+3], d, ar); ah = fma2(wh2[q*4+3], d, ah);
            }
            azR[e] = az; arR[e] = ar; ahR[e] = ah;
        }

        // ===== Stage B2: GRU1 for own elem (kh1 from smem); split chains ====
        u64 azrA = A.azr1b, azrB = 0ull;
        float ahA = A.bg1, ahB = 0.0f;
        {
            const float4* hA4 = (const float4*)(A.h1s + wid * 32);
            #pragma unroll
            for (int j4 = 0; j4 < 8; j4++) {
                const float4 hA = hA4[j4];
                #pragma unroll
                for (int jj = 0; jj < 4; jj++) {
                    const int j = j4 * 4 + jj;
                    const u64 wzr   = ((const u64*)A.kh1zr)[j * 32 + l];
                    const float whv = A.kh1h[j * 32 + l];
                    const float va  = (&hA.x)[jj];
                    if (jj & 1) { azrB = fma2(wzr, dup2(va), azrB); ahB = fmaf(whv, va, ahB); }
                    else        { azrA = fma2(wzr, dup2(va), azrA); ahA = fmaf(whv, va, ahA); }
                }
            }
        }
        {
            float az, ar; unpack2(add2(azrA, azrB), az, ar);
            const float ah1 = ahA + ahB;
            const float z = sigf(xz + az), r = sigf(xr + ar);
            const float hh = tanh_fast(xh + r * ah1);
            h1o = z * h1o + (1.0f - z) * hh;
        }
        __syncwarp();                 // lanes done reading h1s before overwrite
        if (A.owns) A.h1s[wid * 32 + l] = h1o;
        __syncthreads();              // BAR1: h1(t) published; h2s reads done

        // ===== Stage C: xproj2 partials (kx2 rows 8w..8w+8), fold rec2, STS =
        #pragma unroll
        for (int e = 0; e < NE; e++) {
            const float4* hvp = (const float4*)(A.h1s + e * 32 + wid * 8);
            const float4 v0 = hvp[0], v1 = hvp[1];
            u64 az = 0ull, ar = 0ull, ax = 0ull, d;
            d = dup2(v0.x); az = fma2(xw0[0], d, az); ar = fma2(xw1[0], d, ar); ax = fma2(xw2[0], d, ax);
            d = dup2(v0.y); az = fma2(xw0[1], d, az); ar = fma2(xw1[1], d, ar); ax = fma2(xw2[1], d, ax);
            d = dup2(v0.z); az = fma2(xw0[2], d, az); ar = fma2(xw1[2], d, ar); ax = fma2(xw2[2], d, ax);
            d = dup2(v0.w); az = fma2(xw0[3], d, az); ar = fma2(xw1[3], d, ar); ax = fma2(xw2[3], d, ax);
            d = dup2(v1.x); az = fma2(xw0[4], d, az); ar = fma2(xw1[4], d, ar); ax = fma2(xw2[4], d, ax);
            d = dup2(v1.y); az = fma2(xw0[5], d, az); ar = fma2(xw1[5], d, ar); ax = fma2(xw2[5], d, ax);
            d = dup2(v1.z); az = fma2(xw0[6], d, az); ar = fma2(xw1[6], d, ar); ax = fma2(xw2[6], d, ax);
            d = dup2(v1.w); az = fma2(xw0[7], d, az); ar = fma2(xw1[7], d, ar); ax = fma2(xw2[7], d, ax);
            u64* pb = A.pX + (size_t)((e * 4 + wid) * 4) * 32 + l;
            pb[0]  = add2(az, azR[e]);
            pb[32] = add2(ar, arR[e]);
            pb[64] = ax;
            pb[96] = ahR[e];
        }
        __syncthreads();              // BAR2: partials published

        // ===== Stage D: combine own elem, GRU2 gates, publish h2 ============
        if (A.owns) {
            u64 zp = A.bz2, rp = A.br2, xp = A.bxh2, hm = A.bhh2;
            #pragma unroll
            for (int w = 0; w < 4; w++) {
                const u64* pb = A.pX + (size_t)((wid * 4 + w) * 4) * 32 + l;
                zp = add2(zp, pb[0]);
                rp = add2(rp, pb[32]);
                xp = add2(xp, pb[64]);
                hm = add2(hm, pb[96]);
            }
            float zl, zh_, rl, rh_, xpl, xph, ml, mh;
            unpack2(zp, zl, zh_); unpack2(rp, rl, rh_);
            unpack2(xp, xpl, xph); unpack2(hm, ml, mh);
            {
                const float z = sigf(zl), r = sigf(rl);
                const float hh = tanh_fast(xpl + r * ml);
                h2a = z * h2a + (1.0f - z) * hh;
            }
            {
                const float z = sigf(zh_), r = sigf(rh_);
                const float hh = tanh_fast(xph + r * mh);
                h2b = z * h2b + (1.0f - z) * hh;
            }
            A.h2s[wid * 64 + l]      = h2a;
            A.h2s[wid * 64 + 32 + l] = h2b;
        }
        __syncthreads();              // BAR3: h2(t) published; pX reusable
    }
}

__global__ void __launch_bounds__(128, 2) rnn_kernel(
    const int*   __restrict__ tokens,
    const float* __restrict__ kh1, const float* __restrict__ b1,
    const float* __restrict__ kx2, const float* __restrict__ kh2,
    const float* __restrict__ b2,
    const float* __restrict__ wg,  const float* __restrict__ bg,
    const float* __restrict__ wd,  const float* __restrict__ bd,
    float* __restrict__ out)
{
    extern __shared__ float smem[];
    float2* kh1zr = (float2*)smem;                 // [32][32]
    float*  kh1h  = smem + 2048;                   // [32][32]
    u64*    pX    = (u64*)(smem + 3072);           // [4][4][4][32]
    float*  h1s   = smem + 3072 + 4096;            // [4][32]
    float*  h2s   = h1s + 128;                     // [4][64]

    const int tid = threadIdx.x;

    for (int i = tid; i < 1024; i += 128) {
        const int j = i >> 5, c = i & 31;
        kh1zr[i] = make_float2(kh1[j * 96 + c], kh1[j * 96 + 32 + c]);
        kh1h[i]  = kh1[j * 96 + 64 + c];
    }
    if (tid < 128) h1s[tid] = 0.0f;
    for (int i = tid; i < 256; i += 128) h2s[i] = 0.0f;
    __syncthreads();

    const int wid = tid >> 5;
    const int l   = tid & 31;

    // block -> elem range: blocks [0,136) own 4 elems, [136,296) own 3 elems
    const int bid = blockIdx.x;
    const bool big = (bid < 136);
    const int ne   = big ? 4 : 3;
    const int base = big ? bid * 4 : 544 + (bid - 136) * 3;
    const bool owns = (wid < ne);
    const int eg = base + (owns ? wid : ne - 1);   // clamped for safety

    // kh2 rows [16w, 16w+16)
    u64 wz2[16], wr2[16], wh2[16];
    {
        const float* wbase = kh2 + (size_t)(wid * 16) * 192;
        #pragma unroll
        for (int jj = 0; jj < 16; jj++) {
            const float* r = wbase + jj * 192;
            wz2[jj] = pack2(__ldg(r + l),       __ldg(r + 32 + l));
            wr2[jj] = pack2(__ldg(r + 64 + l),  __ldg(r + 96 + l));
            wh2[jj] = pack2(__ldg(r + 128 + l), __ldg(r + 160 + l));
        }
    }
    // kx2 rows [8w, 8w+8)
    u64 xw0[8], xw1[8], xw2[8];
    {
        const float* wbase = kx2 + (size_t)(wid * 8) * 192;
        #pragma unroll
        for (int jj = 0; jj < 8; jj++) {
            const float* r = wbase + jj * 192;
            xw0[jj] = pack2(__ldg(r + l),       __ldg(r + 32 + l));
            xw1[jj] = pack2(__ldg(r + 64 + l),  __ldg(r + 96 + l));
            xw2[jj] = pack2(__ldg(r + 128 + l), __ldg(r + 160 + l));
        }
    }

    RnnArgs A;
    A.tok = tokens + (size_t)eg * NT;
    A.kh1zr = kh1zr; A.kh1h = kh1h; A.pX = pX; A.h1s = h1s; A.h2s = h2s;
    A.wid = wid; A.l = l; A.owns = owns;
    A.azr1b = pack2(__ldg(b1 + 96 + l), __ldg(b1 + 128 + l));
    A.bg1   = __ldg(b1 + 160 + l);
    A.bz2  = pack2(__ldg(b2 + l)      + __ldg(b2 + 192 + l),
                   __ldg(b2 + 32 + l) + __ldg(b2 + 224 + l));
    A.br2  = pack2(__ldg(b2 + 64 + l) + __ldg(b2 + 256 + l),
                   __ldg(b2 + 96 + l) + __ldg(b2 + 288 + l));
    A.bxh2 = pack2(__ldg(b2 + 128 + l), __ldg(b2 + 160 + l));
    A.bhh2 = pack2(__ldg(b2 + 320 + l), __ldg(b2 + 352 + l));

    float h1o = 0.0f, h2a = 0.0f, h2b = 0.0f;

    if (big) rnn_scan<4>(A, wz2, wr2, wh2, xw0, xw1, xw2, h1o, h2a, h2b);
    else     rnn_scan<3>(A, wz2, wr2, wh2, xw0, xw1, xw2, h1o, h2a, h2b);

    // ---------------- head: a = h2@wg + bg ; GLU ; sigmoid(x@wd + bd) -------
    if (owns) {
        const float* h2e = h2s + wid * 64;
        float acc[8];
        #pragma unroll
        for (int k = 0; k < 8; k++) acc[k] = __ldg(bg + l + 32 * k);
        for (int j = 0; j < NU2; j++) {
            const float hv = h2e[j];
            const float* wrp = wg + j * 256 + l;
            #pragma unroll
            for (int k = 0; k < 8; k++) acc[k] = fmaf(hv, __ldg(wrp + 32 * k), acc[k]);
        }
        float s = 0.0f;
        #pragma unroll
        for (int k = 0; k < 4; k++) {
            const float g = acc[k] * sigf(acc[k + 4]);
            s = fmaf(g, __ldg(wd + l + 32 * k), s);
        }
        #pragma unroll
        for (int off = 16; off >= 1; off >>= 1) s += __shfl_xor_sync(0xffffffffu, s, off);
        if (l == 0) out[eg] = sigf(s + __ldg(bd));
    }
}

// ---------------------------------------------------------------------------
extern "C" void kernel_launch(void* const* d_in, const int* in_sizes, int n_in,
                              void* d_out, int out_size) {
    const int*   tokens = (const int*)d_in[0];
    const float* emb = (const float*)d_in[1];
    const float* kx1 = (const float*)d_in[2];
    const float* kh1 = (const float*)d_in[3];
    const float* b1  = (const float*)d_in[4];
    const float* kx2 = (const float*)d_in[5];
    const float* kh2 = (const float*)d_in[6];
    const float* b2  = (const float*)d_in[7];
    const float* wg  = (const float*)d_in[8];
    const float* bg  = (const float*)d_in[9];
    const float* wd  = (const float*)d_in[10];
    const float* bd  = (const float*)d_in[11];
    float* out = (float*)d_out;

    const size_t smem_bytes = SMEM_FLOATS * sizeof(float);
    cudaFuncSetAttribute(rnn_kernel, cudaFuncAttributeMaxDynamicSharedMemorySize, (int)smem_bytes);

    embproj_kernel<<<(VOCAB + 15) / 16, 96>>>(emb, kx1, b1);
    rnn_kernel<<<296, 128, smem_bytes>>>(tokens, kh1, b1, kx2, kh2, b2, wg, bg, wd, bd, out);
}

// round 10
// speedup vs baseline: 1.4527x; 1.0626x over previous
#include <cuda_runtime.h>

constexpr int VOCAB = 50257;
constexpr int DIM   = 50;
constexpr int NU2   = 64;
constexpr int NB    = 1024;
constexpr int NT    = 1024;

using u64 = unsigned long long;

// Precomputed embedding projection: embproj[v][k] = emb[v]@kx1[:,k] + b1[0][k]
// 50257*96 floats = 19.3 MB -> L2 resident during the recurrent kernel.
__device__ float g_embproj[(size_t)VOCAB * 96];

__device__ __forceinline__ u64 pack2(float lo, float hi) {
    u64 r; asm("mov.b64 %0, {%1, %2};" : "=l"(r) : "f"(lo), "f"(hi)); return r;
}
__device__ __forceinline__ u64 dup2(float v) { return pack2(v, v); }
__device__ __forceinline__ void unpack2(u64 p, float& lo, float& hi) {
    asm("mov.b64 {%0, %1}, %2;" : "=f"(lo), "=f"(hi) : "l"(p));
}
__device__ __forceinline__ u64 fma2(u64 a, u64 b, u64 c) {
    u64 d; asm("fma.rn.f32x2 %0, %1, %2, %3;" : "=l"(d) : "l"(a), "l"(b), "l"(c)); return d;
}
__device__ __forceinline__ u64 add2(u64 a, u64 b) {
    u64 d; asm("add.rn.f32x2 %0, %1, %2;" : "=l"(d) : "l"(a), "l"(b)); return d;
}
__device__ __forceinline__ float sigf(float x) {
    return __fdividef(1.0f, 1.0f + __expf(-x));
}
__device__ __forceinline__ float tanh_fast(float x) {
    return 1.0f - __fdividef(2.0f, 1.0f + __expf(2.0f * x));
}

// ---------------------------------------------------------------------------
// Kernel A: embproj = emb @ kx1 + b1[0]
// ---------------------------------------------------------------------------
__global__ void __launch_bounds__(96) embproj_kernel(const float* __restrict__ emb,
                                                     const float* __restrict__ kx1,
                                                     const float* __restrict__ b1) {
    __shared__ float kx1s[DIM * 96];
    __shared__ float xrow[DIM];
    const int tid = threadIdx.x;
    for (int i = tid; i < DIM * 96; i += 96) kx1s[i] = kx1[i];
    const float bc = b1[tid];
    __syncthreads();
    const int row0 = blockIdx.x * 16;
    for (int k = 0; k < 16; k++) {
        const int row = row0 + k;
        if (row >= VOCAB) break;
        if (tid < DIM) xrow[tid] = emb[(size_t)row * DIM + tid];
        __syncthreads();
        float acc = bc;
        #pragma unroll
        for (int d = 0; d < DIM; d++) acc = fmaf(xrow[d], kx1s[d * 96 + tid], acc);
        g_embproj[(size_t)row * 96 + tid] = acc;
        __syncthreads();
    }
}

// ---------------------------------------------------------------------------
// Kernel B: fused GRU1 -> GRU2 -> GLU -> dense.
// 296 blocks x 128 threads (2 CTAs/SM, balanced). Blocks [0,136): 4 elems,
// [136,296): 3 elems; warp w owns elem w (if w < NE).
// ALL weights register-resident, j-split across the 4 warps:
//   kh2 rows [16w,16w+16), kx2 rows [8w,8w+8), kh1 rows [8w,8w+8).
// Cross-step software pipeline (3 barriers per step):
//   Phase A: rec2 partials (h2(t-1)) -> pX slots 3..5;
//            GRU1 combine of rec1 partials (stored last step) -> h1(t); BAR1
//   Phase B: xproj2 partials from h1(t) -> pX slots 0..2;
//            rec1 partials FOR t+1 from the same h1 values -> pR;     BAR2
//   Phase C: combine pX -> GRU2 gates -> h2(t); publish;              BAR3
//
// smem (floats):
//   [0,6144)      pX    u64[4 elems][4 warps][6][32] (xz,xr,xh, rz,rr,rh)
//   [6144,7168)   pRzr  u64[4][4][32]   rec1 z,r partial (paired)
//   [7168,7680)   pRh   f32[4][4][32]   rec1 h partial
//   [7680,7808)   h1s   f32[4][32]
//   [7808,8064)   h2s   f32[4][64]
// ---------------------------------------------------------------------------
constexpr int SMEM_FLOATS = 8064;   // 31.5 KB

template<int NE>
__device__ __forceinline__ void rnn_scan(
    const int* __restrict__ tok, bool owns, int wid, int l,
    u64* pX, u64* pRzr, float* pRh, float* h1s, float* h2s,
    const u64* wz2, const u64* wr2, const u64* wh2,
    const u64* xw0, const u64* xw1, const u64* xw2,
    const u64* k1zr, const float* k1h,
    u64 azr1b, float bg1, u64 bz2, u64 br2, u64 bxh2, u64 bhh2,
    float& h1o, float& h2a, float& h2b)
{
    // --- prologue: embproj gather for t=0 ---
    int tk = 0;
    float xz = 0.0f, xr = 0.0f, xh = 0.0f;
    if (owns) {
        tk = tok[l];
        const int ti = __shfl_sync(0xffffffffu, tk, 0);
        const float* ep = g_embproj + (size_t)ti * 96;
        xz = __ldg(ep + l); xr = __ldg(ep + 32 + l); xh = __ldg(ep + 64 + l);
    }

    for (int t = 0; t < NT; t++) {
        // ===== Phase A: rec2 partials (h2(t-1)) + GRU1 combine =============
        #pragma unroll
        for (int e = 0; e < NE; e++) {
            const float4* hv = (const float4*)(h2s + e * 64 + wid * 16);
            u64 az = 0ull, ar = 0ull, ah = 0ull;
            #pragma unroll
            for (int q = 0; q < 4; q++) {
                const float4 v = hv[q];
                u64 d;
                d = dup2(v.x); az = fma2(wz2[q*4+0], d, az); ar = fma2(wr2[q*4+0], d, ar); ah = fma2(wh2[q*4+0], d, ah);
                d = dup2(v.y); az = fma2(wz2[q*4+1], d, az); ar = fma2(wr2[q*4+1], d, ar); ah = fma2(wh2[q*4+1], d, ah);
                d = dup2(v.z); az = fma2(wz2[q*4+2], d, az); ar = fma2(wr2[q*4+2], d, ar); ah = fma2(wh2[q*4+2], d, ah);
                d = dup2(v.w); az = fma2(wz2[q*4+3], d, az); ar = fma2(wr2[q*4+3], d, ar); ah = fma2(wh2[q*4+3], d, ah);
            }
            u64* pb = pX + (size_t)((e * 4 + wid) * 6) * 32 + l;
            pb[96]  = az;   // slot 3: rec z
            pb[128] = ar;   // slot 4: rec r
            pb[160] = ah;   // slot 5: rec h
        }

        if (owns) {
            // GRU1: combine rec1 partials (written at step t-1; zero at t=0)
            u64 zr = azr1b; float hm = bg1;
            #pragma unroll
            for (int w = 0; w < 4; w++) {
                zr = add2(zr, pRzr[(wid * 4 + w) * 32 + l]);
                hm += pRh[(wid * 4 + w) * 32 + l];
            }
            float az, ar; unpack2(zr, az, ar);
            const float z = sigf(xz + az), r = sigf(xr + ar);
            const float hh = tanh_fast(xh + r * hm);
            h1o = z * h1o + (1.0f - z) * hh;
            h1s[wid * 32 + l] = h1o;
        }

        // prefetch embproj for t+1 (lands long before next Phase A)
        if (owns && t + 1 < NT) {
            if (((t + 1) & 31) == 0) tk = tok[t + 1 + l];
            const int ti = __shfl_sync(0xffffffffu, tk, (t + 1) & 31);
            const float* ep = g_embproj + (size_t)ti * 96;
            xz = __ldg(ep + l); xr = __ldg(ep + 32 + l); xh = __ldg(ep + 64 + l);
        }
        __syncthreads();              // BAR1: h1(t), rec2 partials published

        // ===== Phase B: xproj2 partials + rec1 partials for t+1 ============
        #pragma unroll
        for (int e = 0; e < NE; e++) {
            const float4* hp = (const float4*)(h1s + e * 32 + wid * 8);
            float vv[8];
            *(float4*)(vv)     = hp[0];
            *(float4*)(vv + 4) = hp[1];
            u64 az = 0ull, ar = 0ull, ax = 0ull;
            u64 zr1 = 0ull; float hm1 = 0.0f;
            #pragma unroll
            for (int jj = 0; jj < 8; jj++) {
                const u64 d = dup2(vv[jj]);
                az  = fma2(xw0[jj], d, az);
                ar  = fma2(xw1[jj], d, ar);
                ax  = fma2(xw2[jj], d, ax);
                zr1 = fma2(k1zr[jj], d, zr1);
                hm1 = fmaf(k1h[jj], vv[jj], hm1);
            }
            u64* pb = pX + (size_t)((e * 4 + wid) * 6) * 32 + l;
            pb[0]  = az;    // slot 0: x z
            pb[32] = ar;    // slot 1: x r
            pb[64] = ax;    // slot 2: x h
            pRzr[(e * 4 + wid) * 32 + l] = zr1;
            pRh [(e * 4 + wid) * 32 + l] = hm1;
        }
        __syncthreads();              // BAR2: partials published

        // ===== Phase C: combine -> GRU2 gates -> h2(t) =====================
        if (owns) {
            u64 zp = bz2, rp = br2, xp = bxh2, hm = bhh2;
            #pragma unroll
            for (int w = 0; w < 4; w++) {
                const u64* pb = pX + (size_t)((wid * 4 + w) * 6) * 32 + l;
                zp = add2(zp, pb[0]);
                rp = add2(rp, pb[32]);
                xp = add2(xp, pb[64]);
                zp = add2(zp, pb[96]);
                rp = add2(rp, pb[128]);
                hm = add2(hm, pb[160]);
            }
            float zl, zh_, rl, rh_, xpl, xph, ml, mh;
            unpack2(zp, zl, zh_); unpack2(rp, rl, rh_);
            unpack2(xp, xpl, xph); unpack2(hm, ml, mh);
            {
                const float z = sigf(zl), r = sigf(rl);
                const float hh = tanh_fast(xpl + r * ml);
                h2a = z * h2a + (1.0f - z) * hh;
            }
            {
                const float z = sigf(zh_), r = sigf(rh_);
                const float hh = tanh_fast(xph + r * mh);
                h2b = z * h2b + (1.0f - z) * hh;
            }
            h2s[wid * 64 + l]      = h2a;
            h2s[wid * 64 + 32 + l] = h2b;
        }
        __syncthreads();              // BAR3: h2(t) published
    }
}

__global__ void __launch_bounds__(128, 2) rnn_kernel(
    const int*   __restrict__ tokens,
    const float* __restrict__ kh1, const float* __restrict__ b1,
    const float* __restrict__ kx2, const float* __restrict__ kh2,
    const float* __restrict__ b2,
    const float* __restrict__ wg,  const float* __restrict__ bg,
    const float* __restrict__ wd,  const float* __restrict__ bd,
    float* __restrict__ out)
{
    extern __shared__ float smem[];
    u64*   pX   = (u64*)smem;                 // [4][4][6][32] u64
    u64*   pRzr = pX + 3072;                  // [4][4][32] u64
    float* pRh  = (float*)(pRzr + 512);       // [4][4][32] f32
    float* h1s  = pRh + 512;                  // [4][32]
    float* h2s  = h1s + 128;                  // [4][64]

    const int tid = threadIdx.x;

    // zero-init state + rec1 partial buffers (h(-1) = 0 -> partials = 0)
    for (int i = tid; i < 1024; i += 128) ((float*)pRzr)[i] = 0.0f;   // pRzr
    for (int i = tid; i < 512;  i += 128) pRh[i] = 0.0f;
    if (tid < 128) h1s[tid] = 0.0f;
    for (int i = tid; i < 256; i += 128) h2s[i] = 0.0f;
    __syncthreads();

    const int wid = tid >> 5;
    const int l   = tid & 31;

    // block -> elem range: blocks [0,136) own 4 elems, [136,296) own 3 elems
    const int bid = blockIdx.x;
    const bool big = (bid < 136);
    const int ne   = big ? 4 : 3;
    const int base = big ? bid * 4 : 544 + (bid - 136) * 3;
    const bool owns = (wid < ne);
    const int eg = base + (owns ? wid : ne - 1);   // clamped for safety

    // kh2 rows [16w, 16w+16): lane l owns col pairs (l, l+32) per gate
    u64 wz2[16], wr2[16], wh2[16];
    {
        const float* wbase = kh2 + (size_t)(wid * 16) * 192;
        #pragma unroll
        for (int jj = 0; jj < 16; jj++) {
            const float* r = wbase + jj * 192;
            wz2[jj] = pack2(__ldg(r + l),       __ldg(r + 32 + l));
            wr2[jj] = pack2(__ldg(r + 64 + l),  __ldg(r + 96 + l));
            wh2[jj] = pack2(__ldg(r + 128 + l), __ldg(r + 160 + l));
        }
    }
    // kx2 rows [8w, 8w+8)
    u64 xw0[8], xw1[8], xw2[8];
    {
        const float* wbase = kx2 + (size_t)(wid * 8) * 192;
        #pragma unroll
        for (int jj = 0; jj < 8; jj++) {
            const float* r = wbase + jj * 192;
            xw0[jj] = pack2(__ldg(r + l),       __ldg(r + 32 + l));
            xw1[jj] = pack2(__ldg(r + 64 + l),  __ldg(r + 96 + l));
            xw2[jj] = pack2(__ldg(r + 128 + l), __ldg(r + 160 + l));
        }
    }
    // kh1 rows [8w, 8w+8): z,r paired + h scalar
    u64 k1zr[8]; float k1h[8];
    {
        const float* wbase = kh1 + (size_t)(wid * 8) * 96;
        #pragma unroll
        for (int jj = 0; jj < 8; jj++) {
            const float* r = wbase + jj * 96;
            k1zr[jj] = pack2(__ldg(r + l), __ldg(r + 32 + l));
            k1h[jj]  = __ldg(r + 64 + l);
        }
    }

    // biases
    const u64 azr1b = pack2(__ldg(b1 + 96 + l), __ldg(b1 + 128 + l));
    const float bg1 = __ldg(b1 + 160 + l);
    const u64 bz2  = pack2(__ldg(b2 + l)      + __ldg(b2 + 192 + l),
                           __ldg(b2 + 32 + l) + __ldg(b2 + 224 + l));
    const u64 br2  = pack2(__ldg(b2 + 64 + l) + __ldg(b2 + 256 + l),
                           __ldg(b2 + 96 + l) + __ldg(b2 + 288 + l));
    const u64 bxh2 = pack2(__ldg(b2 + 128 + l), __ldg(b2 + 160 + l));
    const u64 bhh2 = pack2(__ldg(b2 + 320 + l), __ldg(b2 + 352 + l));

    const int* tok = tokens + (size_t)eg * NT;
    float h1o = 0.0f, h2a = 0.0f, h2b = 0.0f;

    if (big) rnn_scan<4>(tok, owns, wid, l, pX, pRzr, pRh, h1s, h2s,
                         wz2, wr2, wh2, xw0, xw1, xw2, k1zr, k1h,
                         azr1b, bg1, bz2, br2, bxh2, bhh2, h1o, h2a, h2b);
    else     rnn_scan<3>(tok, owns, wid, l, pX, pRzr, pRh, h1s, h2s,
                         wz2, wr2, wh2, xw0, xw1, xw2, k1zr, k1h,
                         azr1b, bg1, bz2, br2, bxh2, bhh2, h1o, h2a, h2b);

    // ---------------- head: a = h2@wg + bg ; GLU ; sigmoid(x@wd + bd) -------
    if (owns) {
        const float* h2e = h2s + wid * 64;
        float acc[8];
        #pragma unroll
        for (int k = 0; k < 8; k++) acc[k] = __ldg(bg + l + 32 * k);
        for (int j = 0; j < NU2; j++) {
            const float hv = h2e[j];
            const float* wrp = wg + j * 256 + l;
            #pragma unroll
            for (int k = 0; k < 8; k++) acc[k] = fmaf(hv, __ldg(wrp + 32 * k), acc[k]);
        }
        float s = 0.0f;
        #pragma unroll
        for (int k = 0; k < 4; k++) {
            const float g = acc[k] * sigf(acc[k + 4]);
            s = fmaf(g, __ldg(wd + l + 32 * k), s);
        }
        #pragma unroll
        for (int off = 16; off >= 1; off >>= 1) s += __shfl_xor_sync(0xffffffffu, s, off);
        if (l == 0) out[eg] = sigf(s + __ldg(bd));
    }
}

// ---------------------------------------------------------------------------
extern "C" void kernel_launch(void* const* d_in, const int* in_sizes, int n_in,
                              void* d_out, int out_size) {
    const int*   tokens = (const int*)d_in[0];
    const float* emb = (const float*)d_in[1];
    const float* kx1 = (const float*)d_in[2];
    const float* kh1 = (const float*)d_in[3];
    const float* b1  = (const float*)d_in[4];
    const float* kx2 = (const float*)d_in[5];
    const float* kh2 = (const float*)d_in[6];
    const float* b2  = (const float*)d_in[7];
    const float* wg  = (const float*)d_in[8];
    const float* bg  = (const float*)d_in[9];
    const float* wd  = (const float*)d_in[10];
    const float* bd  = (const float*)d_in[11];
    float* out = (float*)d_out;

    const size_t smem_bytes = SMEM_FLOATS * sizeof(float);
    cudaFuncSetAttribute(rnn_kernel, cudaFuncAttributeMaxDynamicSharedMemorySize, (int)smem_bytes);

    embproj_kernel<<<(VOCAB + 15) / 16, 96>>>(emb, kx1, b1);
    rnn_kernel<<<296, 128, smem_bytes>>>(tokens, kh1, b1, kx2, kh2, b2, wg, bg, wd, bd, out);
}